// round 3
// baseline (speedup 1.0000x reference)
#include <cuda_runtime.h>
#include <cuda_bf16.h>

#define NE 100000
#define NN 10000
#define PI_F 3.14159265358979323846f
#define SQRT_2_CUT 0.6030226891555273f

__device__ int    g_cnt[NN];
__device__ int    g_start[NN];
__device__ int    g_cursor[NN];
__device__ __align__(16) float4 g_pay[2 * NE];

// Per-lane angular exponents (lanes 0..19 meaningful, rest padded to (0,0,0))
__constant__ int c_lx[32] = {0, 1,0,0, 2,1,1,0,0,0, 3,2,2,1,1,1,0,0,0,0, 0,0,0,0,0,0,0,0,0,0,0,0};
__constant__ int c_ly[32] = {0, 0,1,0, 0,1,0,2,1,0, 0,1,0,2,1,0,3,2,1,0, 0,0,0,0,0,0,0,0,0,0,0,0};
__constant__ int c_lz[32] = {0, 0,0,1, 0,0,1,0,1,2, 0,0,1,0,1,2,0,1,2,3, 0,0,0,0,0,0,0,0,0,0,0,0};

__global__ void zero_cnt_kernel() {
    int i = blockIdx.x * blockDim.x + threadIdx.x;
    if (i < NN) g_cnt[i] = 0;
}

__global__ void hist_kernel(const int* __restrict__ ei) {
    int e = blockIdx.x * blockDim.x + threadIdx.x;
    if (e < NE) atomicAdd(&g_cnt[ei[NE + e]], 1);
}

__global__ void scan_kernel() {
    __shared__ int sh[1024];
    int tid = threadIdx.x;
    int base = tid * 10;
    int local[10];
    int sum = 0;
#pragma unroll
    for (int k = 0; k < 10; k++) {
        int idx = base + k;
        int v = (idx < NN) ? g_cnt[idx] : 0;
        local[k] = sum;   // exclusive within-thread
        sum += v;
    }
    sh[tid] = sum;
    __syncthreads();
    for (int d = 1; d < 1024; d <<= 1) {
        int v = (tid >= d) ? sh[tid - d] : 0;
        __syncthreads();
        sh[tid] += v;
        __syncthreads();
    }
    int excl = sh[tid] - sum;
#pragma unroll
    for (int k = 0; k < 10; k++) {
        int idx = base + k;
        if (idx < NN) {
            int v = excl + local[k];
            g_start[idx]  = v;
            g_cursor[idx] = v;
        }
    }
}

__global__ void scatter_kernel(const int* __restrict__ ei,
                               const int* __restrict__ an,
                               const float* __restrict__ el,
                               const float* __restrict__ ev) {
    int e = blockIdx.x * blockDim.x + threadIdx.x;
    if (e >= NE) return;

    int src = ei[e];
    int dst = ei[NE + e];
    int z   = an[src];

    float r  = el[e];
    float vx = ev[3 * e + 0];
    float vy = ev[3 * e + 1];
    float vz = ev[3 * e + 2];
    float inv = rsqrtf(vx * vx + vy * vy + vz * vz);

    float u  = r * (1.0f / 5.5f);
    float u2 = u * u;
    float u3 = u2 * u;
    float u6 = u3 * u3;
    float fc = 1.0f - 28.0f * u6 + 48.0f * u6 * u - 21.0f * u6 * u2;
    fc = (u < 1.0f) ? fc : 0.0f;

    float s, c;
    sincosf(PI_F * u, &s, &c);
    float sc = SQRT_2_CUT / r * fc;
    float scs = z ? -sc : sc;

    int pos = atomicAdd(&g_cursor[dst], 1);
    g_pay[2 * pos + 0] = make_float4(vx * inv, vy * inv, vz * inv, s);
    g_pay[2 * pos + 1] = make_float4(2.0f * c, scs, 0.0f, 0.0f);
}

// Warp-per-node gather + accumulate + contraction + output
__global__ void __launch_bounds__(256) gather_kernel(const int* __restrict__ an,
                                                     const float* __restrict__ W,
                                                     float* __restrict__ out) {
    __shared__ float sh[8 * 320];
    int lane   = threadIdx.x & 31;
    int warpid = threadIdx.x >> 5;
    int node   = (blockIdx.x * blockDim.x + threadIdx.x) >> 5;   // grid exact: 1250*8 = 10000

    int seg_s = g_start[node];
    int n_e   = g_cnt[node];

    int lx = c_lx[lane], ly = c_ly[lane], lz = c_lz[lane];
    bool px1 = (lx == 1), px2 = (lx == 2), px3 = (lx == 3);
    bool py1 = (ly == 1), py2 = (ly == 2), py3 = (ly == 3);
    bool pz1 = (lz == 1), pz2 = (lz == 2), pz3 = (lz == 3);

    float accA[8], accB[8];   // z=0, z=1 accumulators for my angular index, all 8 rbf
#pragma unroll
    for (int n = 0; n < 8; n++) { accA[n] = 0.0f; accB[n] = 0.0f; }

    for (int t = 0; t < n_e; t++) {
        float4 P0 = g_pay[2 * (seg_s + t) + 0];
        float4 P1 = g_pay[2 * (seg_s + t) + 1];
        float x = P0.x, y = P0.y, zc = P0.z, s = P0.w;
        float twoc = P1.x;
        float scs  = P1.y;
        bool  z1   = __float_as_int(scs) < 0;
        float scv  = fabsf(scs);

        float x2 = x * x,  x3 = x2 * x;
        float y2 = y * y,  y3 = y2 * y;
        float z2 = zc * zc, z3 = z2 * zc;

        float xp = px1 ? x : (px2 ? x2 : (px3 ? x3 : 1.0f));
        float yp = py1 ? y : (py2 ? y2 : (py3 ? y3 : 1.0f));
        float zp = pz1 ? zc : (pz2 ? z2 : (pz3 ? z3 : 1.0f));
        float m  = xp * yp * zp * scv;   // my monomial * radial scale

        float m0 = z1 ? 0.0f : m;
        float m1 = z1 ? m : 0.0f;

        float sp = 0.0f, sn = s;
#pragma unroll
        for (int n = 0; n < 8; n++) {
            accA[n] = fmaf(m0, sn, accA[n]);
            accB[n] = fmaf(m1, sn, accB[n]);
            float nx = fmaf(twoc, sn, -sp);
            sp = sn;
            sn = nx;
        }
    }

    // Transpose through shared: layout [z][r][a] per warp
    float* sw = sh + warpid * 320;
    if (lane < 20) {
#pragma unroll
        for (int n = 0; n < 8; n++) {
            sw[n * 20 + lane]       = accA[n];
            sw[160 + n * 20 + lane] = accB[n];
        }
    }
    __syncwarp();

    // r-major epilogue: lane -> (r = lane/4, group g = lane%4 owning a = 5g..5g+4)
    int r = lane >> 2;
    int g = lane & 3;
    const float* p0 = sw + r * 20 + g * 5;
    const float* p1 = p0 + 160;

    float W00 = W[0], W01 = W[1], W02 = W[2];
    float W10 = W[3], W11 = W[4], W12 = W[5];

    float C[5][3];
#pragma unroll
    for (int k = 0; k < 5; k++) {
        float v0 = p0[k], v1 = p1[k];
        C[k][0] = fmaf(v0, W00, v1 * W10);
        C[k][1] = fmaf(v0, W01, v1 * W11);
        C[k][2] = fmaf(v0, W02, v1 * W12);
    }

    float D0[3] = {0, 0, 0}, D1[3] = {0, 0, 0}, D2[3] = {0, 0, 0}, D3[3] = {0, 0, 0};
    if (g == 0) {
        // a = 0..4: levels {0, 1,1,1, 2}, prefs 1
#pragma unroll
        for (int i = 0; i < 3; i++) {
            D0[i] = C[0][i];
            D1[i] = C[1][i] * C[1][i] + C[2][i] * C[2][i] + C[3][i] * C[3][i];
            D2[i] = C[4][i] * C[4][i];
        }
    } else if (g == 1) {
        // a = 5..9: level 2, prefs {2,2,1,2,1}
#pragma unroll
        for (int i = 0; i < 3; i++)
            D2[i] = 2.0f * C[0][i] * C[0][i] + 2.0f * C[1][i] * C[1][i] + C[2][i] * C[2][i]
                  + 2.0f * C[3][i] * C[3][i] + C[4][i] * C[4][i];
    } else if (g == 2) {
        // a = 10..14: level 3, prefs {1,3,3,3,6}
#pragma unroll
        for (int i = 0; i < 3; i++)
            D3[i] = C[0][i] * C[0][i] + 3.0f * C[1][i] * C[1][i] + 3.0f * C[2][i] * C[2][i]
                  + 3.0f * C[3][i] * C[3][i] + 6.0f * C[4][i] * C[4][i];
    } else {
        // a = 15..19: level 3, prefs {3,1,3,3,1}
#pragma unroll
        for (int i = 0; i < 3; i++)
            D3[i] = 3.0f * C[0][i] * C[0][i] + C[1][i] * C[1][i] + 3.0f * C[2][i] * C[2][i]
                  + 3.0f * C[3][i] * C[3][i] + C[4][i] * C[4][i];
    }

    // Reduce across the 4 lanes of this r-group
#pragma unroll
    for (int msk = 1; msk <= 2; msk <<= 1) {
#pragma unroll
        for (int i = 0; i < 3; i++) {
            D0[i] += __shfl_xor_sync(0xffffffffu, D0[i], msk);
            D1[i] += __shfl_xor_sync(0xffffffffu, D1[i], msk);
            D2[i] += __shfl_xor_sync(0xffffffffu, D2[i], msk);
            D3[i] += __shfl_xor_sync(0xffffffffu, D3[i], msk);
        }
    }

    if (g == 0) {
        int   zn = an[node];
        float e0 = zn ? W10 : W00;
        float e1 = zn ? W11 : W01;
        float e2 = zn ? W12 : W02;
        float q0 = e0 * e0, q1 = e1 * e1, q2 = e2 * e2;

        float v[36];
        v[0] = D0[0] * e0;  v[1] = D0[0] * e1;  v[2] = D0[0] * e2;
        v[3] = D0[1] * e0;  v[4] = D0[1] * e1;  v[5] = D0[1] * e2;
        v[6] = D0[2] * e0;  v[7] = D0[2] * e1;  v[8] = D0[2] * e2;

        v[9]  = D1[0] * q0; v[10] = D1[0] * q1; v[11] = D1[0] * q2;
        v[12] = D1[1] * q0; v[13] = D1[1] * q1; v[14] = D1[1] * q2;
        v[15] = D1[2] * q0; v[16] = D1[2] * q1; v[17] = D1[2] * q2;

        v[18] = D2[0] * q0; v[19] = D2[0] * q1; v[20] = D2[0] * q2;
        v[21] = D2[1] * q0; v[22] = D2[1] * q1; v[23] = D2[1] * q2;
        v[24] = D2[2] * q0; v[25] = D2[2] * q1; v[26] = D2[2] * q2;

        v[27] = D3[0] * q0; v[28] = D3[0] * q1; v[29] = D3[0] * q2;
        v[30] = D3[1] * q0; v[31] = D3[1] * q1; v[32] = D3[1] * q2;
        v[33] = D3[2] * q0; v[34] = D3[2] * q1; v[35] = D3[2] * q2;

        float4* o = reinterpret_cast<float4*>(out + (size_t)(node * 8 + r) * 36);
#pragma unroll
        for (int k = 0; k < 9; k++)
            o[k] = make_float4(v[4 * k], v[4 * k + 1], v[4 * k + 2], v[4 * k + 3]);
    }
}

extern "C" void kernel_launch(void* const* d_in, const int* in_sizes, int n_in,
                              void* d_out, int out_size) {
    const int*   an = (const int*)d_in[1];
    const int*   ei = (const int*)d_in[2];
    const float* el = (const float*)d_in[3];
    const float* ev = (const float*)d_in[4];
    const float* W  = (const float*)d_in[5];
    float* out = (float*)d_out;

    zero_cnt_kernel<<<(NN + 255) / 256, 256>>>();
    hist_kernel<<<(NE + 255) / 256, 256>>>(ei);
    scan_kernel<<<1, 1024>>>();
    scatter_kernel<<<(NE + 255) / 256, 256>>>(ei, an, el, ev);
    gather_kernel<<<(NN * 32) / 256, 256>>>(an, W, out);
}

// round 6
// speedup vs baseline: 1.5179x; 1.5179x over previous
#include <cuda_runtime.h>
#include <cuda_bf16.h>

#define NE 100000
#define NN 10000
#define PI_F 3.14159265358979323846f
#define SQRT_2_CUT 0.6030226891555273f

__device__ int    g_cnt[NN];      // statically zero-initialized; re-zeroed by gather each call
__device__ int    g_start[NN];
__device__ int    g_cursor[NN];
__device__ __align__(16) float4 g_pay0[NE];
__device__ __align__(8)  float2 g_pay1[NE];

// Per-lane angular exponents (lanes 0..19 meaningful, rest padded)
__constant__ int c_lx[32] = {0, 1,0,0, 2,1,1,0,0,0, 3,2,2,1,1,1,0,0,0,0, 0,0,0,0,0,0,0,0,0,0,0,0};
__constant__ int c_ly[32] = {0, 0,1,0, 0,1,0,2,1,0, 0,1,0,2,1,0,3,2,1,0, 0,0,0,0,0,0,0,0,0,0,0,0};
__constant__ int c_lz[32] = {0, 0,0,1, 0,0,1,0,1,2, 0,0,1,0,1,2,0,1,2,3, 0,0,0,0,0,0,0,0,0,0,0,0};

__global__ void hist_kernel(const int* __restrict__ ei) {
    int e = blockIdx.x * blockDim.x + threadIdx.x;
    if (e < NE) atomicAdd(&g_cnt[ei[NE + e]], 1);
}

// Single block, 1024 threads. All global traffic coalesced via smem staging.
__global__ void __launch_bounds__(1024) scan_kernel() {
    __shared__ int sh[10240];     // 40KB
    __shared__ int wsum[32];
    int tid = threadIdx.x;

    for (int i = tid; i < 10240; i += 1024) sh[i] = (i < NN) ? g_cnt[i] : 0;
    __syncthreads();

    int base = tid * 10;
    int local[10];
    int sum = 0;
#pragma unroll
    for (int k = 0; k < 10; k++) { local[k] = sum; sum += sh[base + k]; }

    int lane = tid & 31, w = tid >> 5;
    int incl = sum;
#pragma unroll
    for (int d = 1; d < 32; d <<= 1) {
        int v = __shfl_up_sync(0xffffffffu, incl, d);
        if (lane >= d) incl += v;
    }
    if (lane == 31) wsum[w] = incl;
    __syncthreads();
    if (w == 0) {
        int v = wsum[lane];
        int inc2 = v;
#pragma unroll
        for (int d = 1; d < 32; d <<= 1) {
            int t2 = __shfl_up_sync(0xffffffffu, inc2, d);
            if (lane >= d) inc2 += t2;
        }
        wsum[lane] = inc2 - v;   // exclusive warp offsets
    }
    __syncthreads();

    int excl = incl - sum + wsum[w];
#pragma unroll
    for (int k = 0; k < 10; k++) sh[base + k] = excl + local[k];
    __syncthreads();

    for (int i = tid; i < NN; i += 1024) {
        int v = sh[i];
        g_start[i]  = v;
        g_cursor[i] = v;
    }
}

__global__ void __launch_bounds__(256) scatter_kernel(const int* __restrict__ ei,
                                                      const int* __restrict__ an,
                                                      const float* __restrict__ el,
                                                      const float* __restrict__ ev) {
    int e = blockIdx.x * blockDim.x + threadIdx.x;
    if (e >= NE) return;

    int src = ei[e];
    int dst = ei[NE + e];
    float r  = el[e];
    float vx = ev[3 * e + 0];
    float vy = ev[3 * e + 1];
    float vz = ev[3 * e + 2];
    int z = an[src];

    float inv = rsqrtf(vx * vx + vy * vy + vz * vz);

    float u  = r * (1.0f / 5.5f);
    float u2 = u * u;
    float u6 = u2 * u2 * u2;
    float fc = 1.0f - 28.0f * u6 + 48.0f * u6 * u - 21.0f * u6 * u2;
    fc = (u < 1.0f) ? fc : 0.0f;

    float s, c;
    sincosf(PI_F * u, &s, &c);
    float sc  = SQRT_2_CUT / r * fc;
    float scs = z ? -sc : sc;    // z species packed into the sign

    int pos = atomicAdd(&g_cursor[dst], 1);
    g_pay0[pos] = make_float4(vx * inv, vy * inv, vz * inv, s);
    g_pay1[pos] = make_float2(2.0f * c, scs);
}

// Warp-per-node gather + accumulate + contraction + output
__global__ void __launch_bounds__(256) gather_kernel(const int* __restrict__ an,
                                                     const float* __restrict__ W,
                                                     float* __restrict__ out) {
    __shared__ float sh[8 * 320];
    int lane   = threadIdx.x & 31;
    int warpid = threadIdx.x >> 5;
    int node   = (blockIdx.x * blockDim.x + threadIdx.x) >> 5;   // grid exact: 10000 warps

    int seg_s = g_start[node];
    int n_e   = g_cnt[node];
    if (lane == 0) g_cnt[node] = 0;   // restore zeroed state for next replay

    int lx = c_lx[lane], ly = c_ly[lane], lz = c_lz[lane];
    bool px1 = (lx == 1), px2 = (lx == 2), px3 = (lx == 3);
    bool py1 = (ly == 1), py2 = (ly == 2), py3 = (ly == 3);
    bool pz1 = (lz == 1), pz2 = (lz == 2), pz3 = (lz == 3);

    float accS[8], accD[8];   // unsigned-z sum, and z-signed difference
#pragma unroll
    for (int n = 0; n < 8; n++) { accS[n] = 0.0f; accD[n] = 0.0f; }

#pragma unroll 2
    for (int t = 0; t < n_e; t++) {
        float4 P0 = g_pay0[seg_s + t];
        float2 P1 = g_pay1[seg_s + t];
        float x = P0.x, y = P0.y, zc = P0.z, s = P0.w;
        float twoc = P1.x;
        float scs  = P1.y;               // signed: + for z=0, - for z=1

        float x2 = x * x,  x3 = x2 * x;
        float y2 = y * y,  y3 = y2 * y;
        float z2 = zc * zc, z3 = z2 * zc;

        float xp = px1 ? x : (px2 ? x2 : (px3 ? x3 : 1.0f));
        float yp = py1 ? y : (py2 ? y2 : (py3 ? y3 : 1.0f));
        float zp = pz1 ? zc : (pz2 ? z2 : (pz3 ? z3 : 1.0f));
        float mon = xp * yp * zp;            // signed monomial
        float mA  = mon * fabsf(scs);        // species-independent magnitude term
        float mS  = mon * scs;               // species-signed term

        float sp = 0.0f, sn = s;
#pragma unroll
        for (int n = 0; n < 8; n++) {
            accS[n] = fmaf(mA, sn, accS[n]);
            accD[n] = fmaf(mS, sn, accD[n]);
            float nx = fmaf(twoc, sn, -sp);
            sp = sn;
            sn = nx;
        }
    }

    // Transpose through shared: layout [z][r][a] per warp.
    // S0 = (S + D)/2,  S1 = (S - D)/2
    float* sw = sh + warpid * 320;
    if (lane < 20) {
#pragma unroll
        for (int n = 0; n < 8; n++) {
            sw[n * 20 + lane]       = 0.5f * (accS[n] + accD[n]);
            sw[160 + n * 20 + lane] = 0.5f * (accS[n] - accD[n]);
        }
    }
    __syncwarp();

    // r-major epilogue: lane -> (r = lane/4, group g = lane%4 owning a = 5g..5g+4)
    int r = lane >> 2;
    int g = lane & 3;
    const float* p0 = sw + r * 20 + g * 5;
    const float* p1 = p0 + 160;

    float W00 = W[0], W01 = W[1], W02 = W[2];
    float W10 = W[3], W11 = W[4], W12 = W[5];

    float C[5][3];
#pragma unroll
    for (int k = 0; k < 5; k++) {
        float v0 = p0[k], v1 = p1[k];
        C[k][0] = fmaf(v0, W00, v1 * W10);
        C[k][1] = fmaf(v0, W01, v1 * W11);
        C[k][2] = fmaf(v0, W02, v1 * W12);
    }

    float D0[3] = {0, 0, 0}, D1[3] = {0, 0, 0}, D2[3] = {0, 0, 0}, D3[3] = {0, 0, 0};
    if (g == 0) {
#pragma unroll
        for (int i = 0; i < 3; i++) {
            D0[i] = C[0][i];
            D1[i] = C[1][i] * C[1][i] + C[2][i] * C[2][i] + C[3][i] * C[3][i];
            D2[i] = C[4][i] * C[4][i];
        }
    } else if (g == 1) {
#pragma unroll
        for (int i = 0; i < 3; i++)
            D2[i] = 2.0f * C[0][i] * C[0][i] + 2.0f * C[1][i] * C[1][i] + C[2][i] * C[2][i]
                  + 2.0f * C[3][i] * C[3][i] + C[4][i] * C[4][i];
    } else if (g == 2) {
#pragma unroll
        for (int i = 0; i < 3; i++)
            D3[i] = C[0][i] * C[0][i] + 3.0f * C[1][i] * C[1][i] + 3.0f * C[2][i] * C[2][i]
                  + 3.0f * C[3][i] * C[3][i] + 6.0f * C[4][i] * C[4][i];
    } else {
#pragma unroll
        for (int i = 0; i < 3; i++)
            D3[i] = 3.0f * C[0][i] * C[0][i] + C[1][i] * C[1][i] + 3.0f * C[2][i] * C[2][i]
                  + 3.0f * C[3][i] * C[3][i] + C[4][i] * C[4][i];
    }

#pragma unroll
    for (int msk = 1; msk <= 2; msk <<= 1) {
#pragma unroll
        for (int i = 0; i < 3; i++) {
            D0[i] += __shfl_xor_sync(0xffffffffu, D0[i], msk);
            D1[i] += __shfl_xor_sync(0xffffffffu, D1[i], msk);
            D2[i] += __shfl_xor_sync(0xffffffffu, D2[i], msk);
            D3[i] += __shfl_xor_sync(0xffffffffu, D3[i], msk);
        }
    }

    if (g == 0) {
        int   zn = an[node];
        float e0 = zn ? W10 : W00;
        float e1 = zn ? W11 : W01;
        float e2 = zn ? W12 : W02;
        float q0 = e0 * e0, q1 = e1 * e1, q2 = e2 * e2;

        float v[36];
        v[0] = D0[0] * e0;  v[1] = D0[0] * e1;  v[2] = D0[0] * e2;
        v[3] = D0[1] * e0;  v[4] = D0[1] * e1;  v[5] = D0[1] * e2;
        v[6] = D0[2] * e0;  v[7] = D0[2] * e1;  v[8] = D0[2] * e2;

        v[9]  = D1[0] * q0; v[10] = D1[0] * q1; v[11] = D1[0] * q2;
        v[12] = D1[1] * q0; v[13] = D1[1] * q1; v[14] = D1[1] * q2;
        v[15] = D1[2] * q0; v[16] = D1[2] * q1; v[17] = D1[2] * q2;

        v[18] = D2[0] * q0; v[19] = D2[0] * q1; v[20] = D2[0] * q2;
        v[21] = D2[1] * q0; v[22] = D2[1] * q1; v[23] = D2[1] * q2;
        v[24] = D2[2] * q0; v[25] = D2[2] * q1; v[26] = D2[2] * q2;

        v[27] = D3[0] * q0; v[28] = D3[0] * q1; v[29] = D3[0] * q2;
        v[30] = D3[1] * q0; v[31] = D3[1] * q1; v[32] = D3[1] * q2;
        v[33] = D3[2] * q0; v[34] = D3[2] * q1; v[35] = D3[2] * q2;

        float4* o = reinterpret_cast<float4*>(out + (size_t)(node * 8 + r) * 36);
#pragma unroll
        for (int k = 0; k < 9; k++)
            o[k] = make_float4(v[4 * k], v[4 * k + 1], v[4 * k + 2], v[4 * k + 3]);
    }
}

extern "C" void kernel_launch(void* const* d_in, const int* in_sizes, int n_in,
                              void* d_out, int out_size) {
    const int*   an = (const int*)d_in[1];
    const int*   ei = (const int*)d_in[2];
    const float* el = (const float*)d_in[3];
    const float* ev = (const float*)d_in[4];
    const float* W  = (const float*)d_in[5];
    float* out = (float*)d_out;

    hist_kernel<<<(NE + 255) / 256, 256>>>(ei);
    scan_kernel<<<1, 1024>>>();
    scatter_kernel<<<(NE + 255) / 256, 256>>>(ei, an, el, ev);
    gather_kernel<<<(NN * 32) / 256, 256>>>(an, W, out);
}